// round 6
// baseline (speedup 1.0000x reference)
#include <cuda_runtime.h>

#define NDRUG 846
#define EDIM  64
#define SNEI  1024
#define RLEN  100

// ---- scratch (__device__ globals: no allocation allowed) ----
__device__ float g_b2s[SNEI];           // row-sums of b2
__device__ float g_we[NDRUG * EDIM];    // weighted entity embedding per drug

// ---- packed f32x2 FMA (sm_103a): d = a*b + c per 32-bit half
__device__ __forceinline__ unsigned long long fma2(unsigned long long a,
                                                   unsigned long long b,
                                                   unsigned long long c) {
    unsigned long long d;
    asm("fma.rn.f32x2 %0, %1, %2, %3;" : "=l"(d) : "l"(a), "l"(b), "l"(c));
    return d;
}
__device__ __forceinline__ float lo32(unsigned long long v) {
    return __uint_as_float((unsigned)(v & 0xffffffffull));
}
__device__ __forceinline__ float hi32(unsigned long long v) {
    return __uint_as_float((unsigned)(v >> 32));
}

// ------------------------------------------------------------------
// dummy: shifts ncu's sampled launch slot (profiling aid, ~1us)
// ------------------------------------------------------------------
__global__ void k_nop() {}

// ------------------------------------------------------------------
// kernel 0: b2sum[s] = sum_f b2[s,f]
// ------------------------------------------------------------------
__global__ void k_b2sum(const float* __restrict__ b2) {
    int wid = threadIdx.x >> 5, lane = threadIdx.x & 31;
    int s = blockIdx.x * 8 + wid;
    if (s >= SNEI) return;
    float2 v = *reinterpret_cast<const float2*>(b2 + s * 64 + lane * 2);
    float acc = v.x + v.y;
    #pragma unroll
    for (int o = 16; o; o >>= 1) acc += __shfl_xor_sync(0xffffffffu, acc, o);
    if (lane == 0) g_b2s[s] = acc;
}

// ------------------------------------------------------------------
// kernel 1: one CTA per drug.
// smem layout (floats), with post-GEMM overlay onto the W1s region:
//   W1s (e-paired W1') [0, 4096)
//     overlay after GEMM: scores[0,1024) cidx[1024,2048) psum2[2048,2560)
//                         red[2560,2592) cnt[2592]
//   Ms     [4096  , 10496)
//   w2sum  [10496 , 10560)
//   psum0  [10560 , 10816)
#define K1_SMEM_FLOATS 10816
#define K1_SMEM_BYTES  (K1_SMEM_FLOATS * 4)

__global__ void __launch_bounds__(256, 5)
k_drug(const int*   __restrict__ dn,
       const int*   __restrict__ adjt,
       const int*   __restrict__ adjr,
       const float* __restrict__ drug_table,
       const float* __restrict__ rela_table,
       const float* __restrict__ ent_table,
       const float* __restrict__ W1,
       const float* __restrict__ b1,
       const float* __restrict__ W2) {
    extern __shared__ float sm[];
    float* W1s    = sm;           // e-paired: float2 idx (e>>1)*64+f = (W1'[e][f], W1'[e+1][f])
    float* Ms     = sm + 4096;
    float* w2sum  = sm + 10496;
    float* psum0  = sm + 10560;
    // post-GEMM overlay
    float* scores = sm;
    int*   cidx   = (int*)(sm + 1024);
    float* psum2  = sm + 2048;
    float* red    = sm + 2560;
    int*   cntp   = (int*)(sm + 2592);

    const int n    = blockIdx.x;
    const int tid  = threadIdx.x;
    const int wid  = tid >> 5;
    const int lane = tid & 31;

    const int dbase = dn[n] * 64;

    // W1' = diag(drug_emb) * W1, stored e-paired:
    //   W1s floats [(epair*64 + f)*2 + 0/1] = d[2ep]W1[2ep][f] / d[2ep+1]W1[2ep+1][f]
    {
        const float4* src = reinterpret_cast<const float4*>(W1 + (size_t)n * 4096);
        #pragma unroll
        for (int task = tid; task < 512; task += 256) {
            int epair = task >> 4;       // 0..31
            int fq    = task & 15;       // f = fq*4
            float de0 = __ldg(drug_table + dbase + epair * 2);
            float de1 = __ldg(drug_table + dbase + epair * 2 + 1);
            float4 a = src[(epair * 2) * 16 + fq];
            float4 b = src[(epair * 2 + 1) * 16 + fq];
            a.x *= de0; a.y *= de0; a.z *= de0; a.w *= de0;
            b.x *= de1; b.y *= de1; b.z *= de1; b.w *= de1;
            float4* dst = reinterpret_cast<float4*>(W1s + (epair * 64 + fq * 4) * 2);
            dst[0] = make_float4(a.x, b.x, a.y, b.y);
            dst[1] = make_float4(a.z, b.z, a.w, b.w);
        }
    }

    // w2sum partials: thread (f = tid>>2, quarter q = tid&3) sums 16 contiguous
    {
        int f = tid >> 2, q = tid & 3;
        const float4* p = reinterpret_cast<const float4*>(W2 + (size_t)n * 4096 + f * 64 + q * 16);
        float4 a = p[0], b = p[1], c = p[2], d = p[3];
        psum0[tid] = (a.x + a.y + a.z + a.w) + (b.x + b.y + b.z + b.w)
                   + (c.x + c.y + c.z + c.w) + (d.x + d.y + d.z + d.w);
    }
    __syncthreads();
    if (tid < 64)
        w2sum[tid] = psum0[tid * 4] + psum0[tid * 4 + 1] + psum0[tid * 4 + 2] + psum0[tid * 4 + 3];

    // ---- GEMM via packed f32x2: lane owns f = {2*lane, 2*lane+1}
    // accx/accy halves hold (even-e, odd-e) partial sums.
    // rela_table row = 64 floats = 16 ulonglong2 granules (stride 16!)
    const ulonglong2* R2 = reinterpret_cast<const ulonglong2*>(rela_table);
    for (int r0 = wid * 4; r0 <= 96; r0 += 32) {
        unsigned long long accx[4] = {0ull, 0ull, 0ull, 0ull};
        unsigned long long accy[4] = {0ull, 0ull, 0ull, 0ull};
        #pragma unroll 4
        for (int e0 = 0; e0 < 64; e0 += 4) {
            ulonglong2 av[4];
            #pragma unroll
            for (int j = 0; j < 4; j++)
                av[j] = __ldg(&R2[(r0 + j) * 16 + (e0 >> 2)]);
            #pragma unroll
            for (int ep = 0; ep < 2; ep++) {
                // wv.x = (W1'[e][f0], W1'[e+1][f0]); wv.y = same for f1
                ulonglong2 wv = *reinterpret_cast<const ulonglong2*>(
                    W1s + ((e0 >> 1) + ep) * 128 + lane * 4);
                #pragma unroll
                for (int j = 0; j < 4; j++) {
                    unsigned long long a2 = ep ? av[j].y : av[j].x;
                    accx[j] = fma2(a2, wv.x, accx[j]);
                    accy[j] = fma2(a2, wv.y, accy[j]);
                }
            }
        }
        #pragma unroll
        for (int j = 0; j < 4; j++) {
            float sx = lo32(accx[j]) + hi32(accx[j]);
            float sy = lo32(accy[j]) + hi32(accy[j]);
            reinterpret_cast<float2*>(Ms)[(r0 + j) * 32 + lane] = make_float2(sx, sy);
        }
    }
    __syncthreads();   // GEMM done: W1s region is now dead -> overlay live

    // ---- scores: 8-lane group per neighbor; 8 neighbors per unrolled iteration.
    const int g   = lane >> 3;
    const int sub = lane & 7;
    const float4 w2a = *reinterpret_cast<const float4*>(&w2sum[sub * 8]);
    const float4 w2b = *reinterpret_cast<const float4*>(&w2sum[sub * 8 + 4]);
    const float4* Mf4  = reinterpret_cast<const float4*>(Ms);
    const float4* b1f4 = reinterpret_cast<const float4*>(b1);
    const int* adjr_n = adjr + (size_t)n * SNEI;
    for (int sbase = wid * 4; sbase < SNEI; sbase += 64) {
        const int sA = sbase + g;
        const int sB = sbase + 32 + g;
        const int rA = __ldg(adjr_n + sA);
        const int rB = __ldg(adjr_n + sB);
        float4 bA0 = __ldg(&b1f4[sA * 16 + sub * 2]);
        float4 bA1 = __ldg(&b1f4[sA * 16 + sub * 2 + 1]);
        float4 bB0 = __ldg(&b1f4[sB * 16 + sub * 2]);
        float4 bB1 = __ldg(&b1f4[sB * 16 + sub * 2 + 1]);
        float4 mA0 = Mf4[rA * 16 + sub * 2];
        float4 mA1 = Mf4[rA * 16 + sub * 2 + 1];
        float4 mB0 = Mf4[rB * 16 + sub * 2];
        float4 mB1 = Mf4[rB * 16 + sub * 2 + 1];

        float vA, vB;
        vA  = fmaxf(mA0.x + bA0.x, 0.f) * w2a.x;
        vA  = fmaf(fmaxf(mA0.y + bA0.y, 0.f), w2a.y, vA);
        vA  = fmaf(fmaxf(mA0.z + bA0.z, 0.f), w2a.z, vA);
        vA  = fmaf(fmaxf(mA0.w + bA0.w, 0.f), w2a.w, vA);
        vA  = fmaf(fmaxf(mA1.x + bA1.x, 0.f), w2b.x, vA);
        vA  = fmaf(fmaxf(mA1.y + bA1.y, 0.f), w2b.y, vA);
        vA  = fmaf(fmaxf(mA1.z + bA1.z, 0.f), w2b.z, vA);
        vA  = fmaf(fmaxf(mA1.w + bA1.w, 0.f), w2b.w, vA);
        vB  = fmaxf(mB0.x + bB0.x, 0.f) * w2a.x;
        vB  = fmaf(fmaxf(mB0.y + bB0.y, 0.f), w2a.y, vB);
        vB  = fmaf(fmaxf(mB0.z + bB0.z, 0.f), w2a.z, vB);
        vB  = fmaf(fmaxf(mB0.w + bB0.w, 0.f), w2a.w, vB);
        vB  = fmaf(fmaxf(mB1.x + bB1.x, 0.f), w2b.x, vB);
        vB  = fmaf(fmaxf(mB1.y + bB1.y, 0.f), w2b.y, vB);
        vB  = fmaf(fmaxf(mB1.z + bB1.z, 0.f), w2b.z, vB);
        vB  = fmaf(fmaxf(mB1.w + bB1.w, 0.f), w2b.w, vB);
        vA += __shfl_xor_sync(0xffffffffu, vA, 4);
        vB += __shfl_xor_sync(0xffffffffu, vB, 4);
        vA += __shfl_xor_sync(0xffffffffu, vA, 2);
        vB += __shfl_xor_sync(0xffffffffu, vB, 2);
        vA += __shfl_xor_sync(0xffffffffu, vA, 1);
        vB += __shfl_xor_sync(0xffffffffu, vB, 1);
        if (sub == 0) {
            scores[sA] = vA + g_b2s[sA];
            scores[sB] = vB + g_b2s[sB];
        }
    }
    __syncthreads();

    // ---- softmax over 1024 scores (in smem)
    float lm = -1e30f;
    for (int i = tid; i < SNEI; i += 256) lm = fmaxf(lm, scores[i]);
    #pragma unroll
    for (int o = 16; o; o >>= 1) lm = fmaxf(lm, __shfl_xor_sync(0xffffffffu, lm, o));
    if (lane == 0) red[wid] = lm;
    __syncthreads();
    if (tid == 0) {
        float m = red[0];
        #pragma unroll
        for (int i = 1; i < 8; i++) m = fmaxf(m, red[i]);
        red[8] = m;
        *cntp = 0;
    }
    __syncthreads();
    const float mx = red[8];
    float ls = 0.f;
    for (int i = tid; i < SNEI; i += 256) {
        float w = __expf(scores[i] - mx);
        scores[i] = w;
        ls += w;
    }
    #pragma unroll
    for (int o = 16; o; o >>= 1) ls += __shfl_xor_sync(0xffffffffu, ls, o);
    if (lane == 0) red[16 + wid] = ls;
    __syncthreads();
    if (tid == 0) {
        float t = 0.f;
        #pragma unroll
        for (int i = 0; i < 8; i++) t += red[16 + i];
        red[9] = 1.f / t;
    }
    __syncthreads();
    const float inv = red[9];

    // ---- compact surviving neighbors (w > 1e-8), then gather only those
    for (int i = tid; i < SNEI; i += 256) {
        if (scores[i] * inv > 1e-8f) {
            int p = atomicAdd(cntp, 1);
            cidx[p] = i;
        }
    }
    __syncthreads();
    const int C = *cntp;

    float2 acc = make_float2(0.f, 0.f);
    const float2* entf2 = reinterpret_cast<const float2*>(ent_table);
    const int* adjt_n = adjt + (size_t)n * SNEI;
    for (int j = wid; j < C; j += 8) {
        int s = cidx[j];
        float w = scores[s] * inv;           // uniform across warp
        int t = __ldg(adjt_n + s);
        float2 ev = entf2[(size_t)t * 32 + lane];
        acc.x = fmaf(w, ev.x, acc.x);
        acc.y = fmaf(w, ev.y, acc.y);
    }
    reinterpret_cast<float2*>(psum2)[wid * 32 + lane] = acc;
    __syncthreads();
    if (tid < 64) {
        float v = 0.f;
        #pragma unroll
        for (int w = 0; w < 8; w++) v += psum2[w * 64 + tid];
        g_we[n * 64 + tid] = v;
    }
}

// ------------------------------------------------------------------
// kernel 2: one CTA per output feature f.
// ------------------------------------------------------------------
__global__ void __launch_bounds__(256)
k_final(const int*   __restrict__ dn,
        const float* __restrict__ drug_table,
        const float* __restrict__ lin_W,
        const float* __restrict__ lin_b,
        const float* __restrict__ gamma,
        const float* __restrict__ beta,
        float* __restrict__ out) {
    __shared__ float lw[128];
    __shared__ float xcol[NDRUG];
    __shared__ float redbuf[16];
    __shared__ float s_mean, s_scale;

    const int f = blockIdx.x;
    const int tid = threadIdx.x, wid = tid >> 5, lane = tid & 31;

    if (tid < 128) lw[tid] = lin_W[f * 128 + tid];
    __syncthreads();

    const float lb = lin_b[f];
    float lsum = 0.f, lsq = 0.f;
    for (int n = wid; n < NDRUG; n += 8) {
        const float* we = g_we + n * 64;
        int db = dn[n] * 64;
        float v = we[lane] * lw[lane]
                + we[lane + 32] * lw[lane + 32]
                + drug_table[db + lane] * lw[64 + lane]
                + drug_table[db + lane + 32] * lw[96 + lane];
        #pragma unroll
        for (int o = 16; o; o >>= 1) v += __shfl_xor_sync(0xffffffffu, v, o);
        float x = fmaxf(v + lb, 0.f);
        if (lane == 0) { xcol[n] = x; lsum += x; lsq += x * x; }
    }
    if (lane == 0) { redbuf[wid] = lsum; redbuf[8 + wid] = lsq; }
    __syncthreads();
    if (tid == 0) {
        float sm = 0.f, sq = 0.f;
        #pragma unroll
        for (int i = 0; i < 8; i++) { sm += redbuf[i]; sq += redbuf[8 + i]; }
        float mean = sm / (float)NDRUG;
        float var  = sq / (float)NDRUG - mean * mean;
        s_mean  = mean;
        s_scale = rsqrtf(var + 1e-5f) * gamma[f];
    }
    __syncthreads();
    const float mean = s_mean, scal = s_scale, bet = beta[f];
    for (int n = tid; n < NDRUG; n += 256)
        out[n * 64 + f] = (xcol[n] - mean) * scal + bet;
}

// ------------------------------------------------------------------
extern "C" void kernel_launch(void* const* d_in, const int* in_sizes, int n_in,
                              void* d_out, int out_size) {
    const int*   dn         = (const int*)  d_in[0];
    const int*   adjt       = (const int*)  d_in[1];
    const int*   adjr       = (const int*)  d_in[2];
    const float* drug_table = (const float*)d_in[3];
    const float* rela_table = (const float*)d_in[4];
    const float* ent_table  = (const float*)d_in[5];
    const float* W1         = (const float*)d_in[6];
    const float* b1         = (const float*)d_in[7];
    const float* W2         = (const float*)d_in[8];
    const float* b2         = (const float*)d_in[9];
    const float* lin_W      = (const float*)d_in[10];
    const float* lin_b      = (const float*)d_in[11];
    const float* gamma      = (const float*)d_in[12];
    const float* beta       = (const float*)d_in[13];
    float* out = (float*)d_out;

    cudaFuncSetAttribute(k_drug, cudaFuncAttributeMaxDynamicSharedMemorySize, K1_SMEM_BYTES);

    k_nop<<<1, 1>>>();      // shifts ncu's fixed sample slot toward k_drug
    k_b2sum<<<SNEI / 8, 256>>>(b2);
    k_drug<<<NDRUG, 256, K1_SMEM_BYTES>>>(dn, adjt, adjr, drug_table, rela_table,
                                          ent_table, W1, b1, W2);
    k_final<<<EDIM, 256>>>(dn, drug_table, lin_W, lin_b, gamma, beta, out);
}

// round 7
// speedup vs baseline: 1.3768x; 1.3768x over previous
#include <cuda_runtime.h>

#define NDRUG 846
#define EDIM  64
#define SNEI  1024
#define RLEN  100

// ---- scratch (__device__ globals: no allocation allowed) ----
__device__ float g_b2s[SNEI];           // row-sums of b2
__device__ float g_we[NDRUG * EDIM];    // weighted entity embedding per drug
__device__ float g_x[NDRUG * EDIM];     // pre-BN activations
__device__ float g_sum[EDIM];           // per-feature sum (atomic)
__device__ float g_sq[EDIM];            // per-feature sum of squares (atomic)

// ------------------------------------------------------------------
// kernel 0: b2sum[s] = sum_f b2[s,f]; block 0 also zeroes BN accumulators
// ------------------------------------------------------------------
__global__ void k_b2sum(const float* __restrict__ b2) {
    int wid = threadIdx.x >> 5, lane = threadIdx.x & 31;
    if (blockIdx.x == 0 && threadIdx.x < 2 * EDIM) {
        if (threadIdx.x < EDIM) g_sum[threadIdx.x] = 0.f;
        else                    g_sq[threadIdx.x - EDIM] = 0.f;
    }
    int s = blockIdx.x * 8 + wid;
    if (s >= SNEI) return;
    float2 v = *reinterpret_cast<const float2*>(b2 + s * 64 + lane * 2);
    float acc = v.x + v.y;
    #pragma unroll
    for (int o = 16; o; o >>= 1) acc += __shfl_xor_sync(0xffffffffu, acc, o);
    if (lane == 0) g_b2s[s] = acc;
}

// ------------------------------------------------------------------
// kernel 1: one CTA per drug (proven R4 version).
// smem layout (floats), with post-GEMM overlay onto the W1s region:
//   W1s    [0     , 4096 )
//     overlay after GEMM: scores[0,1024) cidx[1024,2048) psum2[2048,2560)
//                         red[2560,2592) cnt[2592]
//   Ms     [4096  , 10496)
//   w2sum  [10496 , 10560)
//   psum0  [10560 , 10816)
#define K1_SMEM_FLOATS 10816
#define K1_SMEM_BYTES  (K1_SMEM_FLOATS * 4)

__global__ void __launch_bounds__(256, 5)
k_drug(const int*   __restrict__ dn,
       const int*   __restrict__ adjt,
       const int*   __restrict__ adjr,
       const float* __restrict__ drug_table,
       const float* __restrict__ rela_table,
       const float* __restrict__ ent_table,
       const float* __restrict__ W1,
       const float* __restrict__ b1,
       const float* __restrict__ W2) {
    extern __shared__ float sm[];
    float* W1s    = sm;
    float* Ms     = sm + 4096;
    float* w2sum  = sm + 10496;
    float* psum0  = sm + 10560;
    // post-GEMM overlay
    float* scores = sm;
    int*   cidx   = (int*)(sm + 1024);
    float* psum2  = sm + 2048;
    float* red    = sm + 2560;
    int*   cntp   = (int*)(sm + 2592);

    const int n    = blockIdx.x;
    const int tid  = threadIdx.x;
    const int wid  = tid >> 5;
    const int lane = tid & 31;

    const int dbase = dn[n] * 64;

    // W1' = diag(drug_emb) * W1  -> smem (row e scaled by d[e])
    {
        const float4* src = reinterpret_cast<const float4*>(W1 + (size_t)n * 4096);
        float4* dst = reinterpret_cast<float4*>(W1s);
        for (int i = tid; i < 1024; i += 256) {
            float4 w = src[i];
            float de = __ldg(drug_table + dbase + (i >> 4));
            w.x *= de; w.y *= de; w.z *= de; w.w *= de;
            dst[i] = w;
        }
    }

    // w2sum partials
    {
        int f = tid >> 2, q = tid & 3;
        const float4* p = reinterpret_cast<const float4*>(W2 + (size_t)n * 4096 + f * 64 + q * 16);
        float4 a = p[0], b = p[1], c = p[2], d = p[3];
        psum0[tid] = (a.x + a.y + a.z + a.w) + (b.x + b.y + b.z + b.w)
                   + (c.x + c.y + c.z + c.w) + (d.x + d.y + d.z + d.w);
    }
    __syncthreads();
    if (tid < 64)
        w2sum[tid] = psum0[tid * 4] + psum0[tid * 4 + 1] + psum0[tid * 4 + 2] + psum0[tid * 4 + 3];

    // ---- GEMM: M[r][f] = sum_e R[r][e] * W1'[e][f]; lane owns f = {2*lane, 2*lane+1}
    const float2* W1f2 = reinterpret_cast<const float2*>(W1s);
    const float4* R4 = reinterpret_cast<const float4*>(rela_table);   // [100][16]
    for (int r0 = wid * 4; r0 <= 96; r0 += 32) {
        float2 acc[4];
        #pragma unroll
        for (int j = 0; j < 4; j++) acc[j] = make_float2(0.f, 0.f);
        #pragma unroll 4
        for (int e0 = 0; e0 < 64; e0 += 4) {
            float a[4][4];
            #pragma unroll
            for (int j = 0; j < 4; j++)
                *reinterpret_cast<float4*>(a[j]) = __ldg(&R4[(r0 + j) * 16 + (e0 >> 2)]);
            #pragma unroll
            for (int ee = 0; ee < 4; ee++) {
                float2 w = W1f2[(e0 + ee) * 32 + lane];
                #pragma unroll
                for (int j = 0; j < 4; j++) {
                    acc[j].x = fmaf(a[j][ee], w.x, acc[j].x);
                    acc[j].y = fmaf(a[j][ee], w.y, acc[j].y);
                }
            }
        }
        #pragma unroll
        for (int j = 0; j < 4; j++)
            reinterpret_cast<float2*>(Ms)[(r0 + j) * 32 + lane] = acc[j];
    }
    __syncthreads();   // GEMM done: W1s region dead -> overlay live

    // ---- scores: 8-lane group per neighbor; 8 neighbors per unrolled iteration.
    const int g   = lane >> 3;
    const int sub = lane & 7;
    const float4 w2a = *reinterpret_cast<const float4*>(&w2sum[sub * 8]);
    const float4 w2b = *reinterpret_cast<const float4*>(&w2sum[sub * 8 + 4]);
    const float4* Mf4  = reinterpret_cast<const float4*>(Ms);
    const float4* b1f4 = reinterpret_cast<const float4*>(b1);
    const int* adjr_n = adjr + (size_t)n * SNEI;
    for (int sbase = wid * 4; sbase < SNEI; sbase += 64) {
        const int sA = sbase + g;
        const int sB = sbase + 32 + g;
        const int rA = __ldg(adjr_n + sA);
        const int rB = __ldg(adjr_n + sB);
        float4 bA0 = __ldg(&b1f4[sA * 16 + sub * 2]);
        float4 bA1 = __ldg(&b1f4[sA * 16 + sub * 2 + 1]);
        float4 bB0 = __ldg(&b1f4[sB * 16 + sub * 2]);
        float4 bB1 = __ldg(&b1f4[sB * 16 + sub * 2 + 1]);
        float4 mA0 = Mf4[rA * 16 + sub * 2];
        float4 mA1 = Mf4[rA * 16 + sub * 2 + 1];
        float4 mB0 = Mf4[rB * 16 + sub * 2];
        float4 mB1 = Mf4[rB * 16 + sub * 2 + 1];

        float vA, vB;
        vA  = fmaxf(mA0.x + bA0.x, 0.f) * w2a.x;
        vA  = fmaf(fmaxf(mA0.y + bA0.y, 0.f), w2a.y, vA);
        vA  = fmaf(fmaxf(mA0.z + bA0.z, 0.f), w2a.z, vA);
        vA  = fmaf(fmaxf(mA0.w + bA0.w, 0.f), w2a.w, vA);
        vA  = fmaf(fmaxf(mA1.x + bA1.x, 0.f), w2b.x, vA);
        vA  = fmaf(fmaxf(mA1.y + bA1.y, 0.f), w2b.y, vA);
        vA  = fmaf(fmaxf(mA1.z + bA1.z, 0.f), w2b.z, vA);
        vA  = fmaf(fmaxf(mA1.w + bA1.w, 0.f), w2b.w, vA);
        vB  = fmaxf(mB0.x + bB0.x, 0.f) * w2a.x;
        vB  = fmaf(fmaxf(mB0.y + bB0.y, 0.f), w2a.y, vB);
        vB  = fmaf(fmaxf(mB0.z + bB0.z, 0.f), w2a.z, vB);
        vB  = fmaf(fmaxf(mB0.w + bB0.w, 0.f), w2a.w, vB);
        vB  = fmaf(fmaxf(mB1.x + bB1.x, 0.f), w2b.x, vB);
        vB  = fmaf(fmaxf(mB1.y + bB1.y, 0.f), w2b.y, vB);
        vB  = fmaf(fmaxf(mB1.z + bB1.z, 0.f), w2b.z, vB);
        vB  = fmaf(fmaxf(mB1.w + bB1.w, 0.f), w2b.w, vB);
        vA += __shfl_xor_sync(0xffffffffu, vA, 4);
        vB += __shfl_xor_sync(0xffffffffu, vB, 4);
        vA += __shfl_xor_sync(0xffffffffu, vA, 2);
        vB += __shfl_xor_sync(0xffffffffu, vB, 2);
        vA += __shfl_xor_sync(0xffffffffu, vA, 1);
        vB += __shfl_xor_sync(0xffffffffu, vB, 1);
        if (sub == 0) {
            scores[sA] = vA + g_b2s[sA];
            scores[sB] = vB + g_b2s[sB];
        }
    }
    __syncthreads();

    // ---- softmax over 1024 scores (in smem)
    float lm = -1e30f;
    for (int i = tid; i < SNEI; i += 256) lm = fmaxf(lm, scores[i]);
    #pragma unroll
    for (int o = 16; o; o >>= 1) lm = fmaxf(lm, __shfl_xor_sync(0xffffffffu, lm, o));
    if (lane == 0) red[wid] = lm;
    __syncthreads();
    if (tid == 0) {
        float m = red[0];
        #pragma unroll
        for (int i = 1; i < 8; i++) m = fmaxf(m, red[i]);
        red[8] = m;
        *cntp = 0;
    }
    __syncthreads();
    const float mx = red[8];
    float ls = 0.f;
    for (int i = tid; i < SNEI; i += 256) {
        float w = __expf(scores[i] - mx);
        scores[i] = w;
        ls += w;
    }
    #pragma unroll
    for (int o = 16; o; o >>= 1) ls += __shfl_xor_sync(0xffffffffu, ls, o);
    if (lane == 0) red[16 + wid] = ls;
    __syncthreads();
    if (tid == 0) {
        float t = 0.f;
        #pragma unroll
        for (int i = 0; i < 8; i++) t += red[16 + i];
        red[9] = 1.f / t;
    }
    __syncthreads();
    const float inv = red[9];

    // ---- compact surviving neighbors (w > 1e-8), then gather only those
    for (int i = tid; i < SNEI; i += 256) {
        if (scores[i] * inv > 1e-8f) {
            int p = atomicAdd(cntp, 1);
            cidx[p] = i;
        }
    }
    __syncthreads();
    const int C = *cntp;

    float2 acc = make_float2(0.f, 0.f);
    const float2* entf2 = reinterpret_cast<const float2*>(ent_table);
    const int* adjt_n = adjt + (size_t)n * SNEI;
    for (int j = wid; j < C; j += 8) {
        int s = cidx[j];
        float w = scores[s] * inv;
        int t = __ldg(adjt_n + s);
        float2 ev = entf2[(size_t)t * 32 + lane];
        acc.x = fmaf(w, ev.x, acc.x);
        acc.y = fmaf(w, ev.y, acc.y);
    }
    reinterpret_cast<float2*>(psum2)[wid * 32 + lane] = acc;
    __syncthreads();
    if (tid < 64) {
        float v = 0.f;
        #pragma unroll
        for (int w = 0; w < 8; w++) v += psum2[w * 64 + tid];
        g_we[n * 64 + tid] = v;
    }
}

// ------------------------------------------------------------------
// kernel 2a: x[n,f] = relu([we;de] . lin_W[f,:] + lin_b[f])  (4 drugs/CTA)
//   thread (d = tid>>6, f = tid&63) computes one full dot via smem-staged
//   transposed lin_W; per-feature sums accumulated for BN via atomics.
// ------------------------------------------------------------------
#define XCTAS ((NDRUG + 3) / 4)   // 212

__global__ void __launch_bounds__(256)
k_xcomp(const int*   __restrict__ dn,
        const float* __restrict__ drug_table,
        const float* __restrict__ lin_W,
        const float* __restrict__ lin_b) {
    __shared__ float lwT[128 * 64];   // lwT[k*64+f] = lin_W[f*128+k]
    __shared__ float vS[4][128];      // concat [we, drug_emb] per drug
    __shared__ float s_sum[64], s_sq[64];

    const int tid = threadIdx.x;
    const int n0  = blockIdx.x * 4;

    // transpose-load lin_W (coalesced global reads, scattered smem writes)
    #pragma unroll
    for (int i = tid; i < 8192; i += 256) {
        int f = i >> 7, k = i & 127;
        lwT[k * 64 + f] = lin_W[i];
    }
    if (tid < 64) { s_sum[tid] = 0.f; s_sq[tid] = 0.f; }

    // stage concat vectors
    #pragma unroll
    for (int i = tid; i < 512; i += 256) {
        int d = i >> 7, k = i & 127;
        int nn = n0 + d;
        float v = 0.f;
        if (nn < NDRUG)
            v = (k < 64) ? g_we[nn * 64 + k]
                         : drug_table[dn[nn] * 64 + (k - 64)];
        vS[d][k] = v;
    }
    __syncthreads();

    const int d = tid >> 6;
    const int f = tid & 63;
    const int nn = n0 + d;

    float acc = 0.f;
    #pragma unroll 8
    for (int k = 0; k < 128; k++)
        acc = fmaf(vS[d][k], lwT[k * 64 + f], acc);
    float x = fmaxf(acc + __ldg(lin_b + f), 0.f);

    if (nn < NDRUG) {
        g_x[nn * 64 + f] = x;
        atomicAdd(&s_sum[f], x);
        atomicAdd(&s_sq[f], x * x);
    }
    __syncthreads();
    if (tid < 64) {
        atomicAdd(&g_sum[tid], s_sum[tid]);
        atomicAdd(&g_sq[tid], s_sq[tid]);
    }
}

// ------------------------------------------------------------------
// kernel 2b: out[n,f] = (x - mean_f) * rsqrt(var_f + eps) * gamma_f + beta_f
// ------------------------------------------------------------------
__global__ void __launch_bounds__(256)
k_bnorm(const float* __restrict__ gamma,
        const float* __restrict__ beta,
        float* __restrict__ out) {
    int idx = blockIdx.x * 256 + threadIdx.x;
    if (idx >= NDRUG * EDIM) return;
    int f = idx & 63;
    float mean = g_sum[f] * (1.f / NDRUG);
    float var  = g_sq[f] * (1.f / NDRUG) - mean * mean;
    float scal = rsqrtf(var + 1e-5f) * __ldg(gamma + f);
    out[idx] = (g_x[idx] - mean) * scal + __ldg(beta + f);
}

// ------------------------------------------------------------------
extern "C" void kernel_launch(void* const* d_in, const int* in_sizes, int n_in,
                              void* d_out, int out_size) {
    const int*   dn         = (const int*)  d_in[0];
    const int*   adjt       = (const int*)  d_in[1];
    const int*   adjr       = (const int*)  d_in[2];
    const float* drug_table = (const float*)d_in[3];
    const float* rela_table = (const float*)d_in[4];
    const float* ent_table  = (const float*)d_in[5];
    const float* W1         = (const float*)d_in[6];
    const float* b1         = (const float*)d_in[7];
    const float* W2         = (const float*)d_in[8];
    const float* b2         = (const float*)d_in[9];
    const float* lin_W      = (const float*)d_in[10];
    const float* lin_b      = (const float*)d_in[11];
    const float* gamma      = (const float*)d_in[12];
    const float* beta       = (const float*)d_in[13];
    float* out = (float*)d_out;

    cudaFuncSetAttribute(k_drug, cudaFuncAttributeMaxDynamicSharedMemorySize, K1_SMEM_BYTES);

    k_b2sum<<<SNEI / 8, 256>>>(b2);                 // also zeroes g_sum/g_sq
    k_drug<<<NDRUG, 256, K1_SMEM_BYTES>>>(dn, adjt, adjr, drug_table, rela_table,
                                          ent_table, W1, b1, W2);
    k_xcomp<<<XCTAS, 256>>>(dn, drug_table, lin_W, lin_b);
    k_bnorm<<<(NDRUG * EDIM + 255) / 256, 256>>>(gamma, beta, out);
}

// round 8
// speedup vs baseline: 1.7378x; 1.2622x over previous
#include <cuda_runtime.h>

#define NDRUG 846
#define EDIM  64
#define SNEI  1024
#define RLEN  100
#define NPAIR (NDRUG / 2)    // 423 (NDRUG is even)

// ---- scratch (__device__ globals: no allocation allowed) ----
__device__ float g_b2s[SNEI];           // row-sums of b2
__device__ float g_we[NDRUG * EDIM];    // weighted entity embedding per drug
__device__ float g_x[NDRUG * EDIM];     // pre-BN activations
__device__ float g_sum[EDIM];           // per-feature sum (atomic)
__device__ float g_sq[EDIM];            // per-feature sum of squares (atomic)

// ------------------------------------------------------------------
// kernel 0: b2sum[s] = sum_f b2[s,f]; block 0 also zeroes BN accumulators
// ------------------------------------------------------------------
__global__ void k_b2sum(const float* __restrict__ b2) {
    int wid = threadIdx.x >> 5, lane = threadIdx.x & 31;
    if (blockIdx.x == 0 && threadIdx.x < 2 * EDIM) {
        if (threadIdx.x < EDIM) g_sum[threadIdx.x] = 0.f;
        else                    g_sq[threadIdx.x - EDIM] = 0.f;
    }
    int s = blockIdx.x * 8 + wid;
    if (s >= SNEI) return;
    float2 v = *reinterpret_cast<const float2*>(b2 + s * 64 + lane * 2);
    float acc = v.x + v.y;
    #pragma unroll
    for (int o = 16; o; o >>= 1) acc += __shfl_xor_sync(0xffffffffu, acc, o);
    if (lane == 0) g_b2s[s] = acc;
}

// ------------------------------------------------------------------
// kernel 1: one CTA per DRUG PAIR (n0 = 2b, n1 = 2b+1).
//   Per drug: GEMM M = R @ (diag(d) W1), w2sum.
//   Score loop reads each b1 row ONCE and scores both drugs (halves L2).
// smem layout (floats):
//   W1s [0,4096) (per-drug staging, reused)
//     overlay after both GEMMs:
//       scores0[0,1024) scores1[1024,2048) cidx[2048,3072)(int)
//       psum2[3072,3584) red[3584,3616) cnt@3616
//   Ms0 [4096,10496)  Ms1 [10496,16896)
//   w2sum0 [16896,16960)  w2sum1 [16960,17024)
//   psum0 [17024,17280)
#define K1_SMEM_FLOATS 17280
#define K1_SMEM_BYTES  (K1_SMEM_FLOATS * 4)

__global__ void __launch_bounds__(256, 3)
k_drug(const int*   __restrict__ dn,
       const int*   __restrict__ adjt,
       const int*   __restrict__ adjr,
       const float* __restrict__ drug_table,
       const float* __restrict__ rela_table,
       const float* __restrict__ ent_table,
       const float* __restrict__ W1,
       const float* __restrict__ b1,
       const float* __restrict__ W2) {
    extern __shared__ float sm[];
    float* W1s    = sm;
    float* Ms0    = sm + 4096;
    float* Ms1    = sm + 10496;
    float* w2s0   = sm + 16896;
    float* w2s1   = sm + 16960;
    float* psum0  = sm + 17024;
    // post-GEMM overlay
    float* scores0 = sm;
    float* scores1 = sm + 1024;
    int*   cidx    = (int*)(sm + 2048);
    float* psum2   = sm + 3072;
    float* red     = sm + 3584;
    int*   cntp    = (int*)(sm + 3616);

    const int n0   = blockIdx.x * 2;
    const int tid  = threadIdx.x;
    const int wid  = tid >> 5;
    const int lane = tid & 31;

    // ================= phase 1: per-drug GEMM + w2sum =================
    #pragma unroll 1
    for (int d = 0; d < 2; d++) {
        const int n = n0 + d;
        const int dbase = dn[n] * 64;
        float* Ms    = d ? Ms1  : Ms0;
        float* w2sum = d ? w2s1 : w2s0;

        // W1' = diag(drug_emb) * W1 -> W1s
        {
            const float4* src = reinterpret_cast<const float4*>(W1 + (size_t)n * 4096);
            float4* dst = reinterpret_cast<float4*>(W1s);
            for (int i = tid; i < 1024; i += 256) {
                float4 w = src[i];
                float de = __ldg(drug_table + dbase + (i >> 4));
                w.x *= de; w.y *= de; w.z *= de; w.w *= de;
                dst[i] = w;
            }
        }
        // w2sum partials
        {
            int f = tid >> 2, q = tid & 3;
            const float4* p = reinterpret_cast<const float4*>(W2 + (size_t)n * 4096 + f * 64 + q * 16);
            float4 a = p[0], b = p[1], c = p[2], e = p[3];
            psum0[tid] = (a.x + a.y + a.z + a.w) + (b.x + b.y + b.z + b.w)
                       + (c.x + c.y + c.z + c.w) + (e.x + e.y + e.z + e.w);
        }
        __syncthreads();
        if (tid < 64)
            w2sum[tid] = psum0[tid * 4] + psum0[tid * 4 + 1] + psum0[tid * 4 + 2] + psum0[tid * 4 + 3];

        // GEMM: M[r][f] = sum_e R[r][e] * W1'[e][f]; lane owns f = {2l, 2l+1}
        const float2* W1f2 = reinterpret_cast<const float2*>(W1s);
        const float4* R4 = reinterpret_cast<const float4*>(rela_table);   // [100][16]
        for (int r0 = wid * 4; r0 <= 96; r0 += 32) {
            float2 acc[4];
            #pragma unroll
            for (int j = 0; j < 4; j++) acc[j] = make_float2(0.f, 0.f);
            #pragma unroll 4
            for (int e0 = 0; e0 < 64; e0 += 4) {
                float a[4][4];
                #pragma unroll
                for (int j = 0; j < 4; j++)
                    *reinterpret_cast<float4*>(a[j]) = __ldg(&R4[(r0 + j) * 16 + (e0 >> 2)]);
                #pragma unroll
                for (int ee = 0; ee < 4; ee++) {
                    float2 w = W1f2[(e0 + ee) * 32 + lane];
                    #pragma unroll
                    for (int j = 0; j < 4; j++) {
                        acc[j].x = fmaf(a[j][ee], w.x, acc[j].x);
                        acc[j].y = fmaf(a[j][ee], w.y, acc[j].y);
                    }
                }
            }
            #pragma unroll
            for (int j = 0; j < 4; j++)
                reinterpret_cast<float2*>(Ms)[(r0 + j) * 32 + lane] = acc[j];
        }
        __syncthreads();   // protects W1s reuse (d=0) / overlay (d=1)
    }

    // ================= phase 2: scores for BOTH drugs, b1 read once ====
    const int g   = lane >> 3;
    const int sub = lane & 7;
    const float4 w2a0 = *reinterpret_cast<const float4*>(&w2s0[sub * 8]);
    const float4 w2b0 = *reinterpret_cast<const float4*>(&w2s0[sub * 8 + 4]);
    const float4 w2a1 = *reinterpret_cast<const float4*>(&w2s1[sub * 8]);
    const float4 w2b1 = *reinterpret_cast<const float4*>(&w2s1[sub * 8 + 4]);
    const float4* M0f4 = reinterpret_cast<const float4*>(Ms0);
    const float4* M1f4 = reinterpret_cast<const float4*>(Ms1);
    const float4* b1f4 = reinterpret_cast<const float4*>(b1);
    const int* adjr0 = adjr + (size_t)n0 * SNEI;
    const int* adjr1 = adjr0 + SNEI;
    for (int sbase = wid * 4; sbase < SNEI; sbase += 32) {
        const int s = sbase + g;
        const int r0i = __ldg(adjr0 + s);
        const int r1i = __ldg(adjr1 + s);
        float4 bv0 = __ldg(&b1f4[s * 16 + sub * 2]);
        float4 bv1 = __ldg(&b1f4[s * 16 + sub * 2 + 1]);
        float4 mA0 = M0f4[r0i * 16 + sub * 2];
        float4 mA1 = M0f4[r0i * 16 + sub * 2 + 1];
        float4 mB0 = M1f4[r1i * 16 + sub * 2];
        float4 mB1 = M1f4[r1i * 16 + sub * 2 + 1];

        float v0, v1;
        v0  = fmaxf(mA0.x + bv0.x, 0.f) * w2a0.x;
        v0  = fmaf(fmaxf(mA0.y + bv0.y, 0.f), w2a0.y, v0);
        v0  = fmaf(fmaxf(mA0.z + bv0.z, 0.f), w2a0.z, v0);
        v0  = fmaf(fmaxf(mA0.w + bv0.w, 0.f), w2a0.w, v0);
        v0  = fmaf(fmaxf(mA1.x + bv1.x, 0.f), w2b0.x, v0);
        v0  = fmaf(fmaxf(mA1.y + bv1.y, 0.f), w2b0.y, v0);
        v0  = fmaf(fmaxf(mA1.z + bv1.z, 0.f), w2b0.z, v0);
        v0  = fmaf(fmaxf(mA1.w + bv1.w, 0.f), w2b0.w, v0);
        v1  = fmaxf(mB0.x + bv0.x, 0.f) * w2a1.x;
        v1  = fmaf(fmaxf(mB0.y + bv0.y, 0.f), w2a1.y, v1);
        v1  = fmaf(fmaxf(mB0.z + bv0.z, 0.f), w2a1.z, v1);
        v1  = fmaf(fmaxf(mB0.w + bv0.w, 0.f), w2a1.w, v1);
        v1  = fmaf(fmaxf(mB1.x + bv1.x, 0.f), w2b1.x, v1);
        v1  = fmaf(fmaxf(mB1.y + bv1.y, 0.f), w2b1.y, v1);
        v1  = fmaf(fmaxf(mB1.z + bv1.z, 0.f), w2b1.z, v1);
        v1  = fmaf(fmaxf(mB1.w + bv1.w, 0.f), w2b1.w, v1);
        v0 += __shfl_xor_sync(0xffffffffu, v0, 4);
        v1 += __shfl_xor_sync(0xffffffffu, v1, 4);
        v0 += __shfl_xor_sync(0xffffffffu, v0, 2);
        v1 += __shfl_xor_sync(0xffffffffu, v1, 2);
        v0 += __shfl_xor_sync(0xffffffffu, v0, 1);
        v1 += __shfl_xor_sync(0xffffffffu, v1, 1);
        if (sub == 0) {
            float bb = g_b2s[s];
            scores0[s] = v0 + bb;
            scores1[s] = v1 + bb;
        }
    }
    __syncthreads();

    // ================= phase 3: softmax + gather (per drug) ============
    #pragma unroll 1
    for (int d = 0; d < 2; d++) {
        float* scores = d ? scores1 : scores0;
        const int n = n0 + d;

        float lm = -1e30f;
        for (int i = tid; i < SNEI; i += 256) lm = fmaxf(lm, scores[i]);
        #pragma unroll
        for (int o = 16; o; o >>= 1) lm = fmaxf(lm, __shfl_xor_sync(0xffffffffu, lm, o));
        if (lane == 0) red[wid] = lm;
        __syncthreads();
        if (tid == 0) {
            float m = red[0];
            #pragma unroll
            for (int i = 1; i < 8; i++) m = fmaxf(m, red[i]);
            red[8] = m;
            *cntp = 0;
        }
        __syncthreads();
        const float mx = red[8];
        float ls = 0.f;
        for (int i = tid; i < SNEI; i += 256) {
            float w = __expf(scores[i] - mx);
            scores[i] = w;
            ls += w;
        }
        #pragma unroll
        for (int o = 16; o; o >>= 1) ls += __shfl_xor_sync(0xffffffffu, ls, o);
        if (lane == 0) red[16 + wid] = ls;
        __syncthreads();
        if (tid == 0) {
            float t = 0.f;
            #pragma unroll
            for (int i = 0; i < 8; i++) t += red[16 + i];
            red[9] = 1.f / t;
        }
        __syncthreads();
        const float inv = red[9];

        // compact surviving neighbors (w > 1e-8)
        for (int i = tid; i < SNEI; i += 256) {
            if (scores[i] * inv > 1e-8f) {
                int p = atomicAdd(cntp, 1);
                cidx[p] = i;
            }
        }
        __syncthreads();
        const int C = *cntp;

        float2 acc = make_float2(0.f, 0.f);
        const float2* entf2 = reinterpret_cast<const float2*>(ent_table);
        const int* adjt_n = adjt + (size_t)n * SNEI;
        for (int j = wid; j < C; j += 8) {
            int s = cidx[j];
            float w = scores[s] * inv;
            int t = __ldg(adjt_n + s);
            float2 ev = entf2[(size_t)t * 32 + lane];
            acc.x = fmaf(w, ev.x, acc.x);
            acc.y = fmaf(w, ev.y, acc.y);
        }
        reinterpret_cast<float2*>(psum2)[wid * 32 + lane] = acc;
        __syncthreads();
        if (tid < 64) {
            float v = 0.f;
            #pragma unroll
            for (int w = 0; w < 8; w++) v += psum2[w * 64 + tid];
            g_we[n * 64 + tid] = v;
        }
        __syncthreads();   // protects cidx/psum2/red reuse for next d
    }
}

// ------------------------------------------------------------------
// kernel 2a: x[n,f] = relu([we;de] . lin_W[f,:] + lin_b[f])  (4 drugs/CTA)
//   lwT padded to stride 65 -> conflict-free transpose store and read.
// ------------------------------------------------------------------
#define XCTAS ((NDRUG + 3) / 4)   // 212

__global__ void __launch_bounds__(256)
k_xcomp(const int*   __restrict__ dn,
        const float* __restrict__ drug_table,
        const float* __restrict__ lin_W,
        const float* __restrict__ lin_b) {
    __shared__ float lwT[128 * 65];   // lwT[k*65+f] = lin_W[f*128+k]
    __shared__ float vS[4][128];      // concat [we, drug_emb] per drug
    __shared__ float s_sum[64], s_sq[64];

    const int tid = threadIdx.x;
    const int n0  = blockIdx.x * 4;

    #pragma unroll
    for (int i = tid; i < 8192; i += 256) {
        int f = i >> 7, k = i & 127;
        lwT[k * 65 + f] = lin_W[i];
    }
    if (tid < 64) { s_sum[tid] = 0.f; s_sq[tid] = 0.f; }

    #pragma unroll
    for (int i = tid; i < 512; i += 256) {
        int d = i >> 7, k = i & 127;
        int nn = n0 + d;
        float v = 0.f;
        if (nn < NDRUG)
            v = (k < 64) ? g_we[nn * 64 + k]
                         : drug_table[dn[nn] * 64 + (k - 64)];
        vS[d][k] = v;
    }
    __syncthreads();

    const int d = tid >> 6;
    const int f = tid & 63;
    const int nn = n0 + d;

    float acc = 0.f;
    #pragma unroll 8
    for (int k = 0; k < 128; k++)
        acc = fmaf(vS[d][k], lwT[k * 65 + f], acc);
    float x = fmaxf(acc + __ldg(lin_b + f), 0.f);

    if (nn < NDRUG) {
        g_x[nn * 64 + f] = x;
        atomicAdd(&s_sum[f], x);
        atomicAdd(&s_sq[f], x * x);
    }
    __syncthreads();
    if (tid < 64) {
        atomicAdd(&g_sum[tid], s_sum[tid]);
        atomicAdd(&g_sq[tid], s_sq[tid]);
    }
}

// ------------------------------------------------------------------
// kernel 2b: out[n,f] = (x - mean_f) * rsqrt(var_f + eps) * gamma_f + beta_f
// ------------------------------------------------------------------
__global__ void __launch_bounds__(256)
k_bnorm(const float* __restrict__ gamma,
        const float* __restrict__ beta,
        float* __restrict__ out) {
    int idx = blockIdx.x * 256 + threadIdx.x;
    if (idx >= NDRUG * EDIM) return;
    int f = idx & 63;
    float mean = g_sum[f] * (1.f / NDRUG);
    float var  = g_sq[f] * (1.f / NDRUG) - mean * mean;
    float scal = rsqrtf(var + 1e-5f) * __ldg(gamma + f);
    out[idx] = (g_x[idx] - mean) * scal + __ldg(beta + f);
}

// ------------------------------------------------------------------
extern "C" void kernel_launch(void* const* d_in, const int* in_sizes, int n_in,
                              void* d_out, int out_size) {
    const int*   dn         = (const int*)  d_in[0];
    const int*   adjt       = (const int*)  d_in[1];
    const int*   adjr       = (const int*)  d_in[2];
    const float* drug_table = (const float*)d_in[3];
    const float* rela_table = (const float*)d_in[4];
    const float* ent_table  = (const float*)d_in[5];
    const float* W1         = (const float*)d_in[6];
    const float* b1         = (const float*)d_in[7];
    const float* W2         = (const float*)d_in[8];
    const float* b2         = (const float*)d_in[9];
    const float* lin_W      = (const float*)d_in[10];
    const float* lin_b      = (const float*)d_in[11];
    const float* gamma      = (const float*)d_in[12];
    const float* beta       = (const float*)d_in[13];
    float* out = (float*)d_out;

    cudaFuncSetAttribute(k_drug, cudaFuncAttributeMaxDynamicSharedMemorySize, K1_SMEM_BYTES);

    k_b2sum<<<SNEI / 8, 256>>>(b2);                 // also zeroes g_sum/g_sq
    k_drug<<<NPAIR, 256, K1_SMEM_BYTES>>>(dn, adjt, adjr, drug_table, rela_table,
                                          ent_table, W1, b1, W2);
    k_xcomp<<<XCTAS, 256>>>(dn, drug_table, lin_W, lin_b);
    k_bnorm<<<(NDRUG * EDIM + 255) / 256, 256>>>(gamma, beta, out);
}

// round 10
// speedup vs baseline: 2.0946x; 1.2053x over previous
#include <cuda_runtime.h>
#include <cuda_bf16.h>
#include <cstdint>

#define NDRUG 846
#define EDIM  64
#define SNEI  1024
#define RLEN  100
#define NPAIR (NDRUG / 2)    // 423

// ---- scratch (__device__ globals: no allocation allowed) ----
__device__ float g_b2s[SNEI];
__device__ float g_we[NDRUG * EDIM];
__device__ float g_x[NDRUG * EDIM];
__device__ float g_sum[EDIM];
__device__ float g_sq[EDIM];
// split-bf16 transposed W1' : [n][f][e] packed 2 bf16 per u32 (even e = low half)
__device__ unsigned g_w1t_hi[NDRUG * 64 * 32];
__device__ unsigned g_w1t_lo[NDRUG * 64 * 32];

__device__ __forceinline__ unsigned pack_bf2(float a, float b) {
    __nv_bfloat16 ha = __float2bfloat16(a), hb = __float2bfloat16(b);
    return (unsigned)__bfloat16_as_ushort(ha) | ((unsigned)__bfloat16_as_ushort(hb) << 16);
}
__device__ __forceinline__ void split2(float x, float& hi, float& lo) {
    __nv_bfloat16 h = __float2bfloat16(x);
    hi = __bfloat162float(h);
    lo = x - hi;
}

// warp-level bf16 mma (baseline PTX, works on plain sm_103 target)
__device__ __forceinline__ void mma16816(float* d, const unsigned* a, const unsigned* b) {
    asm volatile(
        "mma.sync.aligned.m16n8k16.row.col.f32.bf16.bf16.f32 "
        "{%0,%1,%2,%3}, {%4,%5,%6,%7}, {%8,%9}, {%0,%1,%2,%3};"
        : "+f"(d[0]), "+f"(d[1]), "+f"(d[2]), "+f"(d[3])
        : "r"(a[0]), "r"(a[1]), "r"(a[2]), "r"(a[3]), "r"(b[0]), "r"(b[1]));
}

// ------------------------------------------------------------------
// kernel 0: b2sum + zero BN accumulators
// ------------------------------------------------------------------
__global__ void k_b2sum(const float* __restrict__ b2) {
    int wid = threadIdx.x >> 5, lane = threadIdx.x & 31;
    if (blockIdx.x == 0 && threadIdx.x < 2 * EDIM) {
        if (threadIdx.x < EDIM) g_sum[threadIdx.x] = 0.f;
        else                    g_sq[threadIdx.x - EDIM] = 0.f;
    }
    int s = blockIdx.x * 8 + wid;
    if (s >= SNEI) return;
    float2 v = *reinterpret_cast<const float2*>(b2 + s * 64 + lane * 2);
    float acc = v.x + v.y;
    #pragma unroll
    for (int o = 16; o; o >>= 1) acc += __shfl_xor_sync(0xffffffffu, acc, o);
    if (lane == 0) g_b2s[s] = acc;
}

// ------------------------------------------------------------------
// kernel P: per drug, transpose + bf16-split of W1' = diag(d)W1
//   g_w1t_{hi,lo}[n][f*32+ep] = pack(W1'[2ep][f], W1'[2ep+1][f])
// ------------------------------------------------------------------
__global__ void __launch_bounds__(256)
k_prep(const int* __restrict__ dn,
       const float* __restrict__ drug_table,
       const float* __restrict__ W1) {
    __shared__ float t[64 * 65];
    const int n = blockIdx.x;
    const int tid = threadIdx.x;
    const int dbase = dn[n] * 64;
    const float* w1n = W1 + (size_t)n * 4096;

    for (int i = tid; i < 4096; i += 256) {
        int e = i >> 6, f = i & 63;
        t[e * 65 + f] = __ldg(drug_table + dbase + e) * __ldg(w1n + i);
    }
    __syncthreads();
    unsigned* outh = g_w1t_hi + (size_t)n * 2048;
    unsigned* outl = g_w1t_lo + (size_t)n * 2048;
    for (int j = tid; j < 2048; j += 256) {
        int f = j >> 5, ep = j & 31;
        float v0 = t[(2 * ep) * 65 + f];
        float v1 = t[(2 * ep + 1) * 65 + f];
        float h0, l0, h1, l1;
        split2(v0, h0, l0);
        split2(v1, h1, l1);
        outh[f * 32 + ep] = pack_bf2(h0, h1);
        outl[f * 32 + ep] = pack_bf2(l0, l1);
    }
}

// ------------------------------------------------------------------
// kernel 1: one CTA per drug pair. mma.sync bf16 3-term GEMM -> Ms (via
//   register-held D across the staging->overlay barrier), then paired
//   score loop, softmax, compacted gather (R8 structure).
//
// smem u32 layout (staging epoch):
//   A_hi [0,4032) A_lo [4032,8064)       (112 rows x 36, rows>=100 zero)
//   B0h [8064,10368) B0l [10368,12672) B1h [12672,14976) B1l [14976,17280)
// float overlay (post-GEMM epoch):
//   Ms0@0 (100x68) Ms1@6800 scores0@13600 scores1@14624 cidx@15648
//   psum2@16672 red@17184 cnt@17216
// non-overlay floats: w2s0@17280 w2s1@17344 psum0@17408..17664
#define K1_SMEM_FLOATS 17664
#define K1_SMEM_BYTES  (K1_SMEM_FLOATS * 4)
#define A_HI 0
#define A_LO 4032
#define B0H  8064
#define B0L  10368
#define B1H  12672
#define B1L  14976

__global__ void __launch_bounds__(256, 3)
k_drug(const int*   __restrict__ adjt,
       const int*   __restrict__ adjr,
       const float* __restrict__ rela_table,
       const float* __restrict__ ent_table,
       const float* __restrict__ b1,
       const float* __restrict__ W2) {
    extern __shared__ float sm[];
    unsigned* smu = reinterpret_cast<unsigned*>(sm);
    // overlay views
    float* Ms0     = sm;
    float* Ms1     = sm + 6800;
    float* scores0 = sm + 13600;
    float* scores1 = sm + 14624;
    int*   cidx    = (int*)(sm + 15648);
    float* psum2   = sm + 16672;
    float* red     = sm + 17184;
    int*   cntp    = (int*)(sm + 17216);
    // non-overlay
    float* w2s0  = sm + 17280;
    float* w2s1  = sm + 17344;
    float* psum0 = sm + 17408;

    const int n0   = blockIdx.x * 2;
    const int tid  = threadIdx.x;
    const int wid  = tid >> 5;
    const int lane = tid & 31;

    // ---- stage A = split(rela_table), rows 0..99, zero-pad to 112, stride 36
    {
        const float2* Rf2 = reinterpret_cast<const float2*>(rela_table);
        for (int i = tid; i < 112 * 32; i += 256) {
            int row = i >> 5, ep = i & 31;
            unsigned h = 0u, l = 0u;
            if (row < RLEN) {
                float2 v = __ldg(&Rf2[row * 32 + ep]);
                float h0, l0, h1, l1;
                split2(v.x, h0, l0);
                split2(v.y, h1, l1);
                h = pack_bf2(h0, h1);
                l = pack_bf2(l0, l1);
            }
            smu[A_HI + row * 36 + ep] = h;
            smu[A_LO + row * 36 + ep] = l;
        }
    }
    // ---- stage B[d] (already split+transposed by k_prep), stride 36
    #pragma unroll
    for (int d = 0; d < 2; d++) {
        const unsigned* srch = g_w1t_hi + (size_t)(n0 + d) * 2048;
        const unsigned* srcl = g_w1t_lo + (size_t)(n0 + d) * 2048;
        unsigned* dsth = smu + (d ? B1H : B0H);
        unsigned* dstl = smu + (d ? B1L : B0L);
        for (int i = tid; i < 2048; i += 256) {
            int f = i >> 5, ep = i & 31;
            dsth[f * 36 + ep] = __ldg(srch + i);
            dstl[f * 36 + ep] = __ldg(srcl + i);
        }
    }
    // ---- w2sum per drug (disjoint smem; before GEMM)
    #pragma unroll 1
    for (int d = 0; d < 2; d++) {
        int f = tid >> 2, q = tid & 3;
        const float4* p = reinterpret_cast<const float4*>(W2 + (size_t)(n0 + d) * 4096 + f * 64 + q * 16);
        float4 a = p[0], b = p[1], c = p[2], e = p[3];
        psum0[tid] = (a.x + a.y + a.z + a.w) + (b.x + b.y + b.z + b.w)
                   + (c.x + c.y + c.z + c.w) + (e.x + e.y + e.z + e.w);
        __syncthreads();
        if (tid < 64) {
            float* w2 = d ? w2s1 : w2s0;
            w2[tid] = psum0[tid * 4] + psum0[tid * 4 + 1] + psum0[tid * 4 + 2] + psum0[tid * 4 + 3];
        }
        __syncthreads();
    }

    // ---- mma epoch: warp -> (drug = wid>>2, n-quarter q = wid&3)
    const int dsel = wid >> 2;
    const int q    = wid & 3;
    const int g    = lane >> 2;
    const int t    = lane & 3;
    const unsigned* Ah = smu + A_HI;
    const unsigned* Al = smu + A_LO;
    const unsigned* Bh = smu + (dsel ? B1H : B0H);
    const unsigned* Bl = smu + (dsel ? B1L : B0L);

    float D[7][2][4];
    #pragma unroll
    for (int mt = 0; mt < 7; mt++)
        #pragma unroll
        for (int nt = 0; nt < 2; nt++)
            #pragma unroll
            for (int j = 0; j < 4; j++) D[mt][nt][j] = 0.f;

    #pragma unroll
    for (int kp = 0; kp < 32; kp += 8) {       // kp = e-pair base (k0 = 2*kp)
        unsigned bh[2][2], bl[2][2];
        #pragma unroll
        for (int nt = 0; nt < 2; nt++) {
            int fr = q * 16 + nt * 8 + g;
            bh[nt][0] = Bh[fr * 36 + kp + t];
            bh[nt][1] = Bh[fr * 36 + kp + t + 4];
            bl[nt][0] = Bl[fr * 36 + kp + t];
            bl[nt][1] = Bl[fr * 36 + kp + t + 4];
        }
        #pragma unroll
        for (int mt = 0; mt < 7; mt++) {
            int r0 = mt * 16;
            unsigned ah[4], al[4];
            ah[0] = Ah[(r0 + g) * 36 + kp + t];
            ah[1] = Ah[(r0 + g + 8) * 36 + kp + t];
            ah[2] = Ah[(r0 + g) * 36 + kp + t + 4];
            ah[3] = Ah[(r0 + g + 8) * 36 + kp + t + 4];
            al[0] = Al[(r0 + g) * 36 + kp + t];
            al[1] = Al[(r0 + g + 8) * 36 + kp + t];
            al[2] = Al[(r0 + g) * 36 + kp + t + 4];
            al[3] = Al[(r0 + g + 8) * 36 + kp + t + 4];
            #pragma unroll
            for (int nt = 0; nt < 2; nt++) {
                mma16816(D[mt][nt], ah, bh[nt]);
                mma16816(D[mt][nt], ah, bl[nt]);
                mma16816(D[mt][nt], al, bh[nt]);
            }
        }
    }
    __syncthreads();   // staging dead; overlay (Ms) becomes live

    // ---- write D -> Ms (stride 68 floats), rows < 100 only
    {
        float* Msd = dsel ? Ms1 : Ms0;
        #pragma unroll
        for (int mt = 0; mt < 7; mt++) {
            int m0 = mt * 16 + g;
            int m1 = m0 + 8;
            #pragma unroll
            for (int nt = 0; nt < 2; nt++) {
                int f = q * 16 + nt * 8 + 2 * t;
                if (m0 < RLEN)
                    *reinterpret_cast<float2*>(Msd + m0 * 68 + f) =
                        make_float2(D[mt][nt][0], D[mt][nt][1]);
                if (m1 < RLEN)
                    *reinterpret_cast<float2*>(Msd + m1 * 68 + f) =
                        make_float2(D[mt][nt][2], D[mt][nt][3]);
            }
        }
    }
    __syncthreads();

    // ---- scores for BOTH drugs, b1 read once (Ms stride 17 float4)
    const int gg  = lane >> 3;
    const int sub = lane & 7;
    const float4 w2a0 = *reinterpret_cast<const float4*>(&w2s0[sub * 8]);
    const float4 w2b0 = *reinterpret_cast<const float4*>(&w2s0[sub * 8 + 4]);
    const float4 w2a1 = *reinterpret_cast<const float4*>(&w2s1[sub * 8]);
    const float4 w2b1 = *reinterpret_cast<const float4*>(&w2s1[sub * 8 + 4]);
    const float4* M0f4 = reinterpret_cast<const float4*>(Ms0);
    const float4* M1f4 = reinterpret_cast<const float4*>(Ms1);
    const float4* b1f4 = reinterpret_cast<const float4*>(b1);
    const int* adjr0 = adjr + (size_t)n0 * SNEI;
    const int* adjr1 = adjr0 + SNEI;
    for (int sbase = wid * 4; sbase < SNEI; sbase += 32) {
        const int s = sbase + gg;
        const int r0i = __ldg(adjr0 + s);
        const int r1i = __ldg(adjr1 + s);
        float4 bv0 = __ldg(&b1f4[s * 16 + sub * 2]);
        float4 bv1 = __ldg(&b1f4[s * 16 + sub * 2 + 1]);
        float4 mA0 = M0f4[r0i * 17 + sub * 2];
        float4 mA1 = M0f4[r0i * 17 + sub * 2 + 1];
        float4 mB0 = M1f4[r1i * 17 + sub * 2];
        float4 mB1 = M1f4[r1i * 17 + sub * 2 + 1];

        float v0, v1;
        v0  = fmaxf(mA0.x + bv0.x, 0.f) * w2a0.x;
        v0  = fmaf(fmaxf(mA0.y + bv0.y, 0.f), w2a0.y, v0);
        v0  = fmaf(fmaxf(mA0.z + bv0.z, 0.f), w2a0.z, v0);
        v0  = fmaf(fmaxf(mA0.w + bv0.w, 0.f), w2a0.w, v0);
        v0  = fmaf(fmaxf(mA1.x + bv1.x, 0.f), w2b0.x, v0);
        v0  = fmaf(fmaxf(mA1.y + bv1.y, 0.f), w2b0.y, v0);
        v0  = fmaf(fmaxf(mA1.z + bv1.z, 0.f), w2b0.z, v0);
        v0  = fmaf(fmaxf(mA1.w + bv1.w, 0.f), w2b0.w, v0);
        v1  = fmaxf(mB0.x + bv0.x, 0.f) * w2a1.x;
        v1  = fmaf(fmaxf(mB0.y + bv0.y, 0.f), w2a1.y, v1);
        v1  = fmaf(fmaxf(mB0.z + bv0.z, 0.f), w2a1.z, v1);
        v1  = fmaf(fmaxf(mB0.w + bv0.w, 0.f), w2a1.w, v1);
        v1  = fmaf(fmaxf(mB1.x + bv1.x, 0.f), w2b1.x, v1);
        v1  = fmaf(fmaxf(mB1.y + bv1.y, 0.f), w2b1.y, v1);
        v1  = fmaf(fmaxf(mB1.z + bv1.z, 0.f), w2b1.z, v1);
        v1  = fmaf(fmaxf(mB1.w + bv1.w, 0.f), w2b1.w, v1);
        v0 += __shfl_xor_sync(0xffffffffu, v0, 4);
        v1 += __shfl_xor_sync(0xffffffffu, v1, 4);
        v0 += __shfl_xor_sync(0xffffffffu, v0, 2);
        v1 += __shfl_xor_sync(0xffffffffu, v1, 2);
        v0 += __shfl_xor_sync(0xffffffffu, v0, 1);
        v1 += __shfl_xor_sync(0xffffffffu, v1, 1);
        if (sub == 0) {
            float bb = g_b2s[s];
            scores0[s] = v0 + bb;
            scores1[s] = v1 + bb;
        }
    }
    __syncthreads();

    // ---- softmax + compacted gather, per drug
    #pragma unroll 1
    for (int d = 0; d < 2; d++) {
        float* scores = d ? scores1 : scores0;
        const int n = n0 + d;

        float lm = -1e30f;
        for (int i = tid; i < SNEI; i += 256) lm = fmaxf(lm, scores[i]);
        #pragma unroll
        for (int o = 16; o; o >>= 1) lm = fmaxf(lm, __shfl_xor_sync(0xffffffffu, lm, o));
        if (lane == 0) red[wid] = lm;
        __syncthreads();
        if (tid == 0) {
            float m = red[0];
            #pragma unroll
            for (int i = 1; i < 8; i++) m = fmaxf(m, red[i]);
            red[8] = m;
            *cntp = 0;
        }
        __syncthreads();
        const float mx = red[8];
        float ls = 0.f;
        for (int i = tid; i < SNEI; i += 256) {
            float w = __expf(scores[i] - mx);
            scores[i] = w;
            ls += w;
        }
        #pragma unroll
        for (int o = 16; o; o >>= 1) ls += __shfl_xor_sync(0xffffffffu, ls, o);
        if (lane == 0) red[16 + wid] = ls;
        __syncthreads();
        if (tid == 0) {
            float tt = 0.f;
            #pragma unroll
            for (int i = 0; i < 8; i++) tt += red[16 + i];
            red[9] = 1.f / tt;
        }
        __syncthreads();
        const float inv = red[9];

        for (int i = tid; i < SNEI; i += 256) {
            if (scores[i] * inv > 1e-8f) {
                int p = atomicAdd(cntp, 1);
                cidx[p] = i;
            }
        }
        __syncthreads();
        const int C = *cntp;

        float2 acc = make_float2(0.f, 0.f);
        const float2* entf2 = reinterpret_cast<const float2*>(ent_table);
        const int* adjt_n = adjt + (size_t)n * SNEI;
        for (int j = wid; j < C; j += 8) {
            int s = cidx[j];
            float w = scores[s] * inv;
            int tt = __ldg(adjt_n + s);
            float2 ev = entf2[(size_t)tt * 32 + lane];
            acc.x = fmaf(w, ev.x, acc.x);
            acc.y = fmaf(w, ev.y, acc.y);
        }
        reinterpret_cast<float2*>(psum2)[wid * 32 + lane] = acc;
        __syncthreads();
        if (tid < 64) {
            float v = 0.f;
            #pragma unroll
            for (int w = 0; w < 8; w++) v += psum2[w * 64 + tid];
            g_we[n * 64 + tid] = v;
        }
        __syncthreads();
    }
}

// ------------------------------------------------------------------
// kernel 2a: x = relu([we;de] . lin_W^T + lin_b), BN partials (4 drugs/CTA)
// ------------------------------------------------------------------
#define XCTAS ((NDRUG + 3) / 4)

__global__ void __launch_bounds__(256)
k_xcomp(const int*   __restrict__ dn,
        const float* __restrict__ drug_table,
        const float* __restrict__ lin_W,
        const float* __restrict__ lin_b) {
    __shared__ float lwT[128 * 65];
    __shared__ float vS[4][128];
    __shared__ float s_sum[64], s_sq[64];

    const int tid = threadIdx.x;
    const int n0  = blockIdx.x * 4;

    #pragma unroll
    for (int i = tid; i < 8192; i += 256) {
        int f = i >> 7, k = i & 127;
        lwT[k * 65 + f] = lin_W[i];
    }
    if (tid < 64) { s_sum[tid] = 0.f; s_sq[tid] = 0.f; }

    #pragma unroll
    for (int i = tid; i < 512; i += 256) {
        int d = i >> 7, k = i & 127;
        int nn = n0 + d;
        float v = 0.f;
        if (nn < NDRUG)
            v = (k < 64) ? g_we[nn * 64 + k]
                         : drug_table[dn[nn] * 64 + (k - 64)];
        vS[d][k] = v;
    }
    __syncthreads();

    const int d = tid >> 6;
    const int f = tid & 63;
    const int nn = n0 + d;

    float acc = 0.f;
    #pragma unroll 8
    for (int k = 0; k < 128; k++)
        acc = fmaf(vS[d][k], lwT[k * 65 + f], acc);
    float x = fmaxf(acc + __ldg(lin_b + f), 0.f);

    if (nn < NDRUG) {
        g_x[nn * 64 + f] = x;
        atomicAdd(&s_sum[f], x);
        atomicAdd(&s_sq[f], x * x);
    }
    __syncthreads();
    if (tid < 64) {
        atomicAdd(&g_sum[tid], s_sum[tid]);
        atomicAdd(&g_sq[tid], s_sq[tid]);
    }
}

// ------------------------------------------------------------------
// kernel 2b: BN normalize
// ------------------------------------------------------------------
__global__ void __launch_bounds__(256)
k_bnorm(const float* __restrict__ gamma,
        const float* __restrict__ beta,
        float* __restrict__ out) {
    int idx = blockIdx.x * 256 + threadIdx.x;
    if (idx >= NDRUG * EDIM) return;
    int f = idx & 63;
    float mean = g_sum[f] * (1.f / NDRUG);
    float var  = g_sq[f] * (1.f / NDRUG) - mean * mean;
    float scal = rsqrtf(var + 1e-5f) * __ldg(gamma + f);
    out[idx] = (g_x[idx] - mean) * scal + __ldg(beta + f);
}

// ------------------------------------------------------------------
extern "C" void kernel_launch(void* const* d_in, const int* in_sizes, int n_in,
                              void* d_out, int out_size) {
    const int*   dn         = (const int*)  d_in[0];
    const int*   adjt       = (const int*)  d_in[1];
    const int*   adjr       = (const int*)  d_in[2];
    const float* drug_table = (const float*)d_in[3];
    const float* rela_table = (const float*)d_in[4];
    const float* ent_table  = (const float*)d_in[5];
    const float* W1         = (const float*)d_in[6];
    const float* b1         = (const float*)d_in[7];
    const float* W2         = (const float*)d_in[8];
    const float* b2         = (const float*)d_in[9];
    const float* lin_W      = (const float*)d_in[10];
    const float* lin_b      = (const float*)d_in[11];
    const float* gamma      = (const float*)d_in[12];
    const float* beta       = (const float*)d_in[13];
    float* out = (float*)d_out;

    cudaFuncSetAttribute(k_drug, cudaFuncAttributeMaxDynamicSharedMemorySize, K1_SMEM_BYTES);

    k_b2sum<<<SNEI / 8, 256>>>(b2);
    k_prep<<<NDRUG, 256>>>(dn, drug_table, W1);
    k_drug<<<NPAIR, 256, K1_SMEM_BYTES>>>(adjt, adjr, rela_table, ent_table, b1, W2);
    k_xcomp<<<XCTAS, 256>>>(dn, drug_table, lin_W, lin_b);
    k_bnorm<<<(NDRUG * EDIM + 255) / 256, 256>>>(gamma, beta, out);
}

// round 11
// speedup vs baseline: 2.2150x; 1.0575x over previous
#include <cuda_runtime.h>
#include <cuda_bf16.h>
#include <cstdint>

#define NDRUG 846
#define EDIM  64
#define SNEI  1024
#define RLEN  100
#define NPAIR (NDRUG / 2)    // 423

// ---- scratch (__device__ globals: no allocation allowed) ----
__device__ float g_b2s[SNEI];
__device__ float g_we[NDRUG * EDIM];
__device__ float g_x[NDRUG * EDIM];
__device__ float g_sum[EDIM];
__device__ float g_sq[EDIM];

__device__ __forceinline__ unsigned pack_bf2(float a, float b) {
    __nv_bfloat16 ha = __float2bfloat16(a), hb = __float2bfloat16(b);
    return (unsigned)__bfloat16_as_ushort(ha) | ((unsigned)__bfloat16_as_ushort(hb) << 16);
}
__device__ __forceinline__ void split2(float x, float& hi, float& lo) {
    __nv_bfloat16 h = __float2bfloat16(x);
    hi = __bfloat162float(h);
    lo = x - hi;
}

// warp-level bf16 mma (baseline PTX, works on plain sm_103 target)
__device__ __forceinline__ void mma16816(float* d, const unsigned* a, const unsigned* b) {
    asm volatile(
        "mma.sync.aligned.m16n8k16.row.col.f32.bf16.bf16.f32 "
        "{%0,%1,%2,%3}, {%4,%5,%6,%7}, {%8,%9}, {%0,%1,%2,%3};"
        : "+f"(d[0]), "+f"(d[1]), "+f"(d[2]), "+f"(d[3])
        : "r"(a[0]), "r"(a[1]), "r"(a[2]), "r"(a[3]), "r"(b[0]), "r"(b[1]));
}

// ------------------------------------------------------------------
// kernel 0: b2sum + zero BN accumulators
// ------------------------------------------------------------------
__global__ void k_b2sum(const float* __restrict__ b2) {
    int wid = threadIdx.x >> 5, lane = threadIdx.x & 31;
    if (blockIdx.x == 0 && threadIdx.x < 2 * EDIM) {
        if (threadIdx.x < EDIM) g_sum[threadIdx.x] = 0.f;
        else                    g_sq[threadIdx.x - EDIM] = 0.f;
    }
    int s = blockIdx.x * 8 + wid;
    if (s >= SNEI) return;
    float2 v = *reinterpret_cast<const float2*>(b2 + s * 64 + lane * 2);
    float acc = v.x + v.y;
    #pragma unroll
    for (int o = 16; o; o >>= 1) acc += __shfl_xor_sync(0xffffffffu, acc, o);
    if (lane == 0) g_b2s[s] = acc;
}

// ------------------------------------------------------------------
// kernel 1: one CTA per drug pair.
//   In-CTA W1 transpose+split (temp in A region), mma.sync bf16 3-term
//   GEMM -> Ms (D register-held across overlay barrier), paired score
//   loop, softmax, compacted gather.
//
// smem u32 layout (staging epoch):
//   A_hi [0,4032) A_lo [4032,8064)       (112 rows x 36, rows>=100 zero)
//     (A region doubles as fp32 temp[64*66] during B prep, BEFORE A staged)
//   B0h [8064,10368) B0l [10368,12672) B1h [12672,14976) B1l [14976,17280)
// float overlay (post-GEMM epoch):
//   Ms0@0 (100x68) Ms1@6800 scores0@13600 scores1@14624 cidx@15648
//   psum2@16672 red@17184 cnt@17216
// non-overlay floats: w2s0@17280 w2s1@17344 psum0@17408..17664
#define K1_SMEM_FLOATS 17664
#define K1_SMEM_BYTES  (K1_SMEM_FLOATS * 4)
#define A_HI 0
#define A_LO 4032
#define B0H  8064
#define B0L  10368
#define B1H  12672
#define B1L  14976

__global__ void __launch_bounds__(256, 3)
k_drug(const int*   __restrict__ dn,
       const int*   __restrict__ adjt,
       const int*   __restrict__ adjr,
       const float* __restrict__ drug_table,
       const float* __restrict__ rela_table,
       const float* __restrict__ ent_table,
       const float* __restrict__ W1,
       const float* __restrict__ b1,
       const float* __restrict__ W2) {
    extern __shared__ float sm[];
    unsigned* smu = reinterpret_cast<unsigned*>(sm);
    // overlay views
    float* Ms0     = sm;
    float* Ms1     = sm + 6800;
    float* scores0 = sm + 13600;
    float* scores1 = sm + 14624;
    int*   cidx    = (int*)(sm + 15648);
    float* psum2   = sm + 16672;
    float* red     = sm + 17184;
    int*   cntp    = (int*)(sm + 17216);
    // non-overlay
    float* w2s0  = sm + 17280;
    float* w2s1  = sm + 17344;
    float* psum0 = sm + 17408;

    const int n0   = blockIdx.x * 2;
    const int tid  = threadIdx.x;
    const int wid  = tid >> 5;
    const int lane = tid & 31;

    // ---- B prep (fused k_prep): temp transpose in the A region ----
    {
        float* temp = sm;   // 64*66 = 4224 floats, fits u32[0,8064)
        #pragma unroll 1
        for (int d = 0; d < 2; d++) {
            const int n = n0 + d;
            const int dbase = dn[n] * 64;
            const float* w1n = W1 + (size_t)n * 4096;
            for (int i = tid; i < 4096; i += 256) {
                int e = i >> 6, f = i & 63;
                temp[e * 66 + f] = __ldg(drug_table + dbase + e) * __ldg(w1n + i);
            }
            __syncthreads();
            unsigned* dsth = smu + (d ? B1H : B0H);
            unsigned* dstl = smu + (d ? B1L : B0L);
            for (int j = tid; j < 2048; j += 256) {
                int f = j >> 5, ep = j & 31;
                float v0 = temp[(2 * ep) * 66 + f];
                float v1 = temp[(2 * ep + 1) * 66 + f];
                float h0, l0, h1, l1;
                split2(v0, h0, l0);
                split2(v1, h1, l1);
                dsth[f * 36 + ep] = pack_bf2(h0, h1);
                dstl[f * 36 + ep] = pack_bf2(l0, l1);
            }
            __syncthreads();
        }
    }

    // ---- stage A = split(rela_table), rows 0..99, zero-pad to 112, stride 36
    {
        const float2* Rf2 = reinterpret_cast<const float2*>(rela_table);
        for (int i = tid; i < 112 * 32; i += 256) {
            int row = i >> 5, ep = i & 31;
            unsigned h = 0u, l = 0u;
            if (row < RLEN) {
                float2 v = __ldg(&Rf2[row * 32 + ep]);
                float h0, l0, h1, l1;
                split2(v.x, h0, l0);
                split2(v.y, h1, l1);
                h = pack_bf2(h0, h1);
                l = pack_bf2(l0, l1);
            }
            smu[A_HI + row * 36 + ep] = h;
            smu[A_LO + row * 36 + ep] = l;
        }
    }
    // ---- w2sum per drug (disjoint smem; before GEMM)
    #pragma unroll 1
    for (int d = 0; d < 2; d++) {
        int f = tid >> 2, q = tid & 3;
        const float4* p = reinterpret_cast<const float4*>(W2 + (size_t)(n0 + d) * 4096 + f * 64 + q * 16);
        float4 a = p[0], b = p[1], c = p[2], e = p[3];
        psum0[tid] = (a.x + a.y + a.z + a.w) + (b.x + b.y + b.z + b.w)
                   + (c.x + c.y + c.z + c.w) + (e.x + e.y + e.z + e.w);
        __syncthreads();
        if (tid < 64) {
            float* w2 = d ? w2s1 : w2s0;
            w2[tid] = psum0[tid * 4] + psum0[tid * 4 + 1] + psum0[tid * 4 + 2] + psum0[tid * 4 + 3];
        }
        __syncthreads();
    }

    // ---- mma epoch: warp -> (drug = wid>>2, n-quarter q = wid&3)
    const int dsel = wid >> 2;
    const int q    = wid & 3;
    const int g    = lane >> 2;
    const int t    = lane & 3;
    const unsigned* Ah = smu + A_HI;
    const unsigned* Al = smu + A_LO;
    const unsigned* Bh = smu + (dsel ? B1H : B0H);
    const unsigned* Bl = smu + (dsel ? B1L : B0L);

    float D[7][2][4];
    #pragma unroll
    for (int mt = 0; mt < 7; mt++)
        #pragma unroll
        for (int nt = 0; nt < 2; nt++)
            #pragma unroll
            for (int j = 0; j < 4; j++) D[mt][nt][j] = 0.f;

    #pragma unroll
    for (int kp = 0; kp < 32; kp += 8) {       // kp = e-pair base
        unsigned bh[2][2], bl[2][2];
        #pragma unroll
        for (int nt = 0; nt < 2; nt++) {
            int fr = q * 16 + nt * 8 + g;
            bh[nt][0] = Bh[fr * 36 + kp + t];
            bh[nt][1] = Bh[fr * 36 + kp + t + 4];
            bl[nt][0] = Bl[fr * 36 + kp + t];
            bl[nt][1] = Bl[fr * 36 + kp + t + 4];
        }
        #pragma unroll
        for (int mt = 0; mt < 7; mt++) {
            int r0 = mt * 16;
            unsigned ah[4], al[4];
            ah[0] = Ah[(r0 + g) * 36 + kp + t];
            ah[1] = Ah[(r0 + g + 8) * 36 + kp + t];
            ah[2] = Ah[(r0 + g) * 36 + kp + t + 4];
            ah[3] = Ah[(r0 + g + 8) * 36 + kp + t + 4];
            al[0] = Al[(r0 + g) * 36 + kp + t];
            al[1] = Al[(r0 + g + 8) * 36 + kp + t];
            al[2] = Al[(r0 + g) * 36 + kp + t + 4];
            al[3] = Al[(r0 + g + 8) * 36 + kp + t + 4];
            #pragma unroll
            for (int nt = 0; nt < 2; nt++) {
                mma16816(D[mt][nt], ah, bh[nt]);
                mma16816(D[mt][nt], ah, bl[nt]);
                mma16816(D[mt][nt], al, bh[nt]);
            }
        }
    }
    __syncthreads();   // staging dead; overlay (Ms) becomes live

    // ---- write D -> Ms (stride 68 floats), rows < 100 only
    {
        float* Msd = dsel ? Ms1 : Ms0;
        #pragma unroll
        for (int mt = 0; mt < 7; mt++) {
            int m0 = mt * 16 + g;
            int m1 = m0 + 8;
            #pragma unroll
            for (int nt = 0; nt < 2; nt++) {
                int f = q * 16 + nt * 8 + 2 * t;
                if (m0 < RLEN)
                    *reinterpret_cast<float2*>(Msd + m0 * 68 + f) =
                        make_float2(D[mt][nt][0], D[mt][nt][1]);
                if (m1 < RLEN)
                    *reinterpret_cast<float2*>(Msd + m1 * 68 + f) =
                        make_float2(D[mt][nt][2], D[mt][nt][3]);
            }
        }
    }
    __syncthreads();

    // ---- scores for BOTH drugs, b1 read once (Ms stride 17 float4)
    const int gg  = lane >> 3;
    const int sub = lane & 7;
    const float4 w2a0 = *reinterpret_cast<const float4*>(&w2s0[sub * 8]);
    const float4 w2b0 = *reinterpret_cast<const float4*>(&w2s0[sub * 8 + 4]);
    const float4 w2a1 = *reinterpret_cast<const float4*>(&w2s1[sub * 8]);
    const float4 w2b1 = *reinterpret_cast<const float4*>(&w2s1[sub * 8 + 4]);
    const float4* M0f4 = reinterpret_cast<const float4*>(Ms0);
    const float4* M1f4 = reinterpret_cast<const float4*>(Ms1);
    const float4* b1f4 = reinterpret_cast<const float4*>(b1);
    const int* adjr0 = adjr + (size_t)n0 * SNEI;
    const int* adjr1 = adjr0 + SNEI;
    for (int sbase = wid * 4; sbase < SNEI; sbase += 32) {
        const int s = sbase + gg;
        const int r0i = __ldg(adjr0 + s);
        const int r1i = __ldg(adjr1 + s);
        float4 bv0 = __ldg(&b1f4[s * 16 + sub * 2]);
        float4 bv1 = __ldg(&b1f4[s * 16 + sub * 2 + 1]);
        float4 mA0 = M0f4[r0i * 17 + sub * 2];
        float4 mA1 = M0f4[r0i * 17 + sub * 2 + 1];
        float4 mB0 = M1f4[r1i * 17 + sub * 2];
        float4 mB1 = M1f4[r1i * 17 + sub * 2 + 1];

        float v0, v1;
        v0  = fmaxf(mA0.x + bv0.x, 0.f) * w2a0.x;
        v0  = fmaf(fmaxf(mA0.y + bv0.y, 0.f), w2a0.y, v0);
        v0  = fmaf(fmaxf(mA0.z + bv0.z, 0.f), w2a0.z, v0);
        v0  = fmaf(fmaxf(mA0.w + bv0.w, 0.f), w2a0.w, v0);
        v0  = fmaf(fmaxf(mA1.x + bv1.x, 0.f), w2b0.x, v0);
        v0  = fmaf(fmaxf(mA1.y + bv1.y, 0.f), w2b0.y, v0);
        v0  = fmaf(fmaxf(mA1.z + bv1.z, 0.f), w2b0.z, v0);
        v0  = fmaf(fmaxf(mA1.w + bv1.w, 0.f), w2b0.w, v0);
        v1  = fmaxf(mB0.x + bv0.x, 0.f) * w2a1.x;
        v1  = fmaf(fmaxf(mB0.y + bv0.y, 0.f), w2a1.y, v1);
        v1  = fmaf(fmaxf(mB0.z + bv0.z, 0.f), w2a1.z, v1);
        v1  = fmaf(fmaxf(mB0.w + bv0.w, 0.f), w2a1.w, v1);
        v1  = fmaf(fmaxf(mB1.x + bv1.x, 0.f), w2b1.x, v1);
        v1  = fmaf(fmaxf(mB1.y + bv1.y, 0.f), w2b1.y, v1);
        v1  = fmaf(fmaxf(mB1.z + bv1.z, 0.f), w2b1.z, v1);
        v1  = fmaf(fmaxf(mB1.w + bv1.w, 0.f), w2b1.w, v1);
        v0 += __shfl_xor_sync(0xffffffffu, v0, 4);
        v1 += __shfl_xor_sync(0xffffffffu, v1, 4);
        v0 += __shfl_xor_sync(0xffffffffu, v0, 2);
        v1 += __shfl_xor_sync(0xffffffffu, v1, 2);
        v0 += __shfl_xor_sync(0xffffffffu, v0, 1);
        v1 += __shfl_xor_sync(0xffffffffu, v1, 1);
        if (sub == 0) {
            float bb = g_b2s[s];
            scores0[s] = v0 + bb;
            scores1[s] = v1 + bb;
        }
    }
    __syncthreads();

    // ---- softmax + compacted gather, per drug
    #pragma unroll 1
    for (int d = 0; d < 2; d++) {
        float* scores = d ? scores1 : scores0;
        const int n = n0 + d;

        float lm = -1e30f;
        for (int i = tid; i < SNEI; i += 256) lm = fmaxf(lm, scores[i]);
        #pragma unroll
        for (int o = 16; o; o >>= 1) lm = fmaxf(lm, __shfl_xor_sync(0xffffffffu, lm, o));
        if (lane == 0) red[wid] = lm;
        __syncthreads();
        if (tid == 0) {
            float m = red[0];
            #pragma unroll
            for (int i = 1; i < 8; i++) m = fmaxf(m, red[i]);
            red[8] = m;
            *cntp = 0;
        }
        __syncthreads();
        const float mx = red[8];
        float ls = 0.f;
        for (int i = tid; i < SNEI; i += 256) {
            float w = __expf(scores[i] - mx);
            scores[i] = w;
            ls += w;
        }
        #pragma unroll
        for (int o = 16; o; o >>= 1) ls += __shfl_xor_sync(0xffffffffu, ls, o);
        if (lane == 0) red[16 + wid] = ls;
        __syncthreads();
        if (tid == 0) {
            float tt = 0.f;
            #pragma unroll
            for (int i = 0; i < 8; i++) tt += red[16 + i];
            red[9] = 1.f / tt;
        }
        __syncthreads();
        const float inv = red[9];

        for (int i = tid; i < SNEI; i += 256) {
            if (scores[i] * inv > 1e-8f) {
                int p = atomicAdd(cntp, 1);
                cidx[p] = i;
            }
        }
        __syncthreads();
        const int C = *cntp;

        float2 acc = make_float2(0.f, 0.f);
        const float2* entf2 = reinterpret_cast<const float2*>(ent_table);
        const int* adjt_n = adjt + (size_t)n * SNEI;
        for (int j = wid; j < C; j += 8) {
            int s = cidx[j];
            float w = scores[s] * inv;
            int tt = __ldg(adjt_n + s);
            float2 ev = entf2[(size_t)tt * 32 + lane];
            acc.x = fmaf(w, ev.x, acc.x);
            acc.y = fmaf(w, ev.y, acc.y);
        }
        reinterpret_cast<float2*>(psum2)[wid * 32 + lane] = acc;
        __syncthreads();
        if (tid < 64) {
            float v = 0.f;
            #pragma unroll
            for (int w = 0; w < 8; w++) v += psum2[w * 64 + tid];
            g_we[n * 64 + tid] = v;
        }
        __syncthreads();
    }
}

// ------------------------------------------------------------------
// kernel 2a: x = relu([we;de] . lin_W^T + lin_b), BN partials (4 drugs/CTA)
// ------------------------------------------------------------------
#define XCTAS ((NDRUG + 3) / 4)

__global__ void __launch_bounds__(256)
k_xcomp(const int*   __restrict__ dn,
        const float* __restrict__ drug_table,
        const float* __restrict__ lin_W,
        const float* __restrict__ lin_b) {
    __shared__ float lwT[128 * 65];
    __shared__ float vS[4][128];
    __shared__ float s_sum[64], s_sq[64];

    const int tid = threadIdx.x;
    const int n0  = blockIdx.x * 4;

    #pragma unroll
    for (int i = tid; i < 8192; i += 256) {
        int f = i >> 7, k = i & 127;
        lwT[k * 65 + f] = lin_W[i];
    }
    if (tid < 64) { s_sum[tid] = 0.f; s_sq[tid] = 0.f; }

    #pragma unroll
    for (int i = tid; i < 512; i += 256) {
        int d = i >> 7, k = i & 127;
        int nn = n0 + d;
        float v = 0.f;
        if (nn < NDRUG)
            v = (k < 64) ? g_we[nn * 64 + k]
                         : drug_table[dn[nn] * 64 + (k - 64)];
        vS[d][k] = v;
    }
    __syncthreads();

    const int d = tid >> 6;
    const int f = tid & 63;
    const int nn = n0 + d;

    float acc = 0.f;
    #pragma unroll 8
    for (int k = 0; k < 128; k++)
        acc = fmaf(vS[d][k], lwT[k * 65 + f], acc);
    float x = fmaxf(acc + __ldg(lin_b + f), 0.f);

    if (nn < NDRUG) {
        g_x[nn * 64 + f] = x;
        atomicAdd(&s_sum[f], x);
        atomicAdd(&s_sq[f], x * x);
    }
    __syncthreads();
    if (tid < 64) {
        atomicAdd(&g_sum[tid], s_sum[tid]);
        atomicAdd(&g_sq[tid], s_sq[tid]);
    }
}

// ------------------------------------------------------------------
// kernel 2b: BN normalize
// ------------------------------------------------------------------
__global__ void __launch_bounds__(256)
k_bnorm(const float* __restrict__ gamma,
        const float* __restrict__ beta,
        float* __restrict__ out) {
    int idx = blockIdx.x * 256 + threadIdx.x;
    if (idx >= NDRUG * EDIM) return;
    int f = idx & 63;
    float mean = g_sum[f] * (1.f / NDRUG);
    float var  = g_sq[f] * (1.f / NDRUG) - mean * mean;
    float scal = rsqrtf(var + 1e-5f) * __ldg(gamma + f);
    out[idx] = (g_x[idx] - mean) * scal + __ldg(beta + f);
}

// ------------------------------------------------------------------
extern "C" void kernel_launch(void* const* d_in, const int* in_sizes, int n_in,
                              void* d_out, int out_size) {
    const int*   dn         = (const int*)  d_in[0];
    const int*   adjt       = (const int*)  d_in[1];
    const int*   adjr       = (const int*)  d_in[2];
    const float* drug_table = (const float*)d_in[3];
    const float* rela_table = (const float*)d_in[4];
    const float* ent_table  = (const float*)d_in[5];
    const float* W1         = (const float*)d_in[6];
    const float* b1         = (const float*)d_in[7];
    const float* W2         = (const float*)d_in[8];
    const float* b2         = (const float*)d_in[9];
    const float* lin_W      = (const float*)d_in[10];
    const float* lin_b      = (const float*)d_in[11];
    const float* gamma      = (const float*)d_in[12];
    const float* beta       = (const float*)d_in[13];
    float* out = (float*)d_out;

    cudaFuncSetAttribute(k_drug, cudaFuncAttributeMaxDynamicSharedMemorySize, K1_SMEM_BYTES);

    k_b2sum<<<SNEI / 8, 256>>>(b2);
    k_drug<<<NPAIR, 256, K1_SMEM_BYTES>>>(dn, adjt, adjr, drug_table, rela_table,
                                          ent_table, W1, b1, W2);
    k_xcomp<<<XCTAS, 256>>>(dn, drug_table, lin_W, lin_b);
    k_bnorm<<<(NDRUG * EDIM + 255) / 256, 256>>>(gamma, beta, out);
}